// round 7
// baseline (speedup 1.0000x reference)
#include <cuda_runtime.h>
#include <math.h>

#define BSZ 256
#define HSZ 256
#define TIN 336
#define TOUT 96
#define FSZ 32

// ---------------- device-global scratch (allocation-free) ----------------
// activations stored as (hi, lo) tf32 split, feature-index swizzled
__device__ float g_h0hi[2][BSZ * HSZ], g_h0lo[2][BSZ * HSZ];
__device__ float g_h1hi[2][BSZ * HSZ], g_h1lo[2][BSZ * HSZ];
__device__ float g_c0[BSZ * HSZ], g_c1[BSZ * HSZ];
__device__ float g_xhi[BSZ * TIN * FSZ], g_xlo[BSZ * TIN * FSZ];
__device__ float g_Wp[4 * HSZ * HSZ];   // dec_Wih0 @ dec_Wout (fp32, pre-pack)
__device__ float g_bp[4 * HSZ];         // dec_b0 + dec_Wih0 @ dec_bout
__device__ float g_h1s[(size_t)TOUT * BSZ * HSZ]; // decoder h1 per step (fp32)

// packed+swizzled hi/lo weights: layout [1024 packed rows][K]
__device__ float g_eWih0h[1024 * 32],  g_eWih0l[1024 * 32];
__device__ float g_eWhh0h[1024 * 256], g_eWhh0l[1024 * 256];
__device__ float g_eWih1h[1024 * 256], g_eWih1l[1024 * 256];
__device__ float g_eWhh1h[1024 * 256], g_eWhh1l[1024 * 256];
__device__ float g_dWih0h[1024 * 32],  g_dWih0l[1024 * 32];
__device__ float g_dWhh0h[1024 * 256], g_dWhh0l[1024 * 256];
__device__ float g_dWih1h[1024 * 256], g_dWih1l[1024 * 256];
__device__ float g_dWhh1h[1024 * 256], g_dWhh1l[1024 * 256];
__device__ float g_Wph[1024 * 256],    g_Wpl[1024 * 256];

// ---------------- helpers ----------------
__device__ __forceinline__ unsigned f2tf32(float v) {
  unsigned r;
  asm("cvt.rna.tf32.f32 %0, %1;" : "=r"(r) : "f"(v));
  return r;
}
__device__ __forceinline__ void tf32_split(float v, float& hi, float& lo) {
  unsigned hb = f2tf32(v);
  hi = __uint_as_float(hb);
  float l = v - hi;
  lo = __uint_as_float(f2tf32(l));
}
// swizzle within 8-group so that (k, k+4) land adjacent: perm(kin)=(kin&3)*2+(kin>>2)
__device__ __forceinline__ int ksw(int k) {
  return (k & ~7) | (((k & 3) << 1) | ((k >> 2) & 1));
}
// inverse: given swizzled pos c, original kin
__device__ __forceinline__ int kunsw(int c) {
  return (c & ~7) | (((c & 1) << 2) | ((c & 7) >> 1));
}

#define FB(x) __float_as_uint(x)
#define MMA_TF32(C, A, B0, B1)                                              \
  asm volatile(                                                             \
      "mma.sync.aligned.m16n8k8.row.col.f32.tf32.tf32.f32 "                 \
      "{%0,%1,%2,%3},{%4,%5,%6,%7},{%8,%9},{%0,%1,%2,%3};"                  \
      : "+f"(C[0]), "+f"(C[1]), "+f"(C[2]), "+f"(C[3])                      \
      : "r"(A[0]), "r"(A[1]), "r"(A[2]), "r"(A[3]), "r"(B0), "r"(B1))

// ---------------- init / preprocess kernels ----------------
__global__ void zero_init_kernel() {
  int i = blockIdx.x * blockDim.x + threadIdx.x;
  g_h0hi[0][i] = 0.f; g_h0lo[0][i] = 0.f;
  g_h1hi[0][i] = 0.f; g_h1lo[0][i] = 0.f;
  g_c0[i] = 0.f; g_c1[i] = 0.f;
}

__global__ void wp_kernel(const float* __restrict__ Wih0,
                          const float* __restrict__ Wout) {
  __shared__ float wr[FSZ];
  int c = blockIdx.x;                    // gate row 0..1023
  if (threadIdx.x < FSZ) wr[threadIdx.x] = Wih0[c * FSZ + threadIdx.x];
  __syncthreads();
  int k = threadIdx.x;                   // hidden col 0..255
  float acc = 0.f;
#pragma unroll
  for (int f = 0; f < FSZ; ++f) acc += wr[f] * Wout[f * HSZ + k];
  g_Wp[c * HSZ + k] = acc;
}

__global__ void bp_kernel(const float* __restrict__ Wih0,
                          const float* __restrict__ b0,
                          const float* __restrict__ bout) {
  int c = blockIdx.x * blockDim.x + threadIdx.x;
  float acc = b0[c];
#pragma unroll
  for (int f = 0; f < FSZ; ++f) acc += Wih0[c * FSZ + f] * bout[f];
  g_bp[c] = acc;
}

// pack weights: out[pr][c] (pr = by*64 + n; orig row r = (n>>4)*256 + by*16 + (n&15);
// orig col = kunsw(c)); split into tf32 hi/lo
__global__ void pack_w(const float* __restrict__ W, int K,
                       float* __restrict__ ohi, float* __restrict__ olo) {
  int idx = blockIdx.x * 256 + threadIdx.x;
  if (idx >= 1024 * K) return;
  int pr = idx / K, c = idx % K;
  int n = pr & 63, by = pr >> 6;
  int r = (n >> 4) * 256 + by * 16 + (n & 15);
  float v = W[r * K + kunsw(c)];
  float hi, lo;
  tf32_split(v, hi, lo);
  ohi[idx] = hi; olo[idx] = lo;
}

__global__ void pack_x(const float* __restrict__ x) {
  int idx = blockIdx.x * 256 + threadIdx.x;  // BSZ*TIN*FSZ = 2752512
  int c = idx & 31, base = idx & ~31;
  float v = x[base + kunsw(c)];
  float hi, lo;
  tf32_split(v, hi, lo);
  g_xhi[idx] = hi; g_xlo[idx] = lo;
}

// ---------------- fused LSTM cell step (tf32x3 MMA) ----------------
// gates[B,4H] = A[B,D]@Wih^T + hin[B,H]@Whh^T + bias;  then pointwise.
// CTA: 128 threads (4 warps), tile 32 batch x 64 gate-cols.
// Warps 2x2: wm=(wid&1)*16, wn=(wid>>1)*32.  Grid (8,16)=128 CTAs.
__global__ __launch_bounds__(128) void lstm_step_mma(
    const float* __restrict__ Ahi, const float* __restrict__ Alo, int lda, int D,
    const float* __restrict__ Wih_hi, const float* __restrict__ Wih_lo,
    const float* __restrict__ hin_hi, const float* __restrict__ hin_lo,
    const float* __restrict__ Whh_hi, const float* __restrict__ Whh_lo,
    const float* __restrict__ bias,
    float* __restrict__ c_state,
    float* __restrict__ out_hi, float* __restrict__ out_lo,
    float* __restrict__ out_f32) {
  // sAh [0,1280) sAl [1280,2560) sWh [2560,5120) sWl [5120,7680)  (pitch 40)
  __shared__ __align__(16) float sm[7680];
  float* sAh = sm;
  float* sAl = sm + 1280;
  float* sWh = sm + 2560;
  float* sWl = sm + 5120;

  int tid = threadIdx.x;
  int row0 = blockIdx.x * 32;
  int by = blockIdx.y;
  int lane = tid & 31, wid = tid >> 5;
  int g = lane >> 2, q = lane & 3;
  int wm = (wid & 1) * 16, wn = (wid >> 1) * 32;
  float c[4][4] = {};

  for (int seg = 0; seg < 2; ++seg) {
    const float* ah = seg ? hin_hi : Ahi;
    const float* al = seg ? hin_lo : Alo;
    int ld = seg ? HSZ : lda;
    int K = seg ? HSZ : D;
    const float* wh = (seg ? Whh_hi : Wih_hi) + (size_t)by * 64 * K;
    const float* wl = (seg ? Whh_lo : Wih_lo) + (size_t)by * 64 * K;

    for (int k0 = 0; k0 < K; k0 += 32) {
      __syncthreads();
      {  // A tile 32x32 (hi+lo), already swizzled in global
        int r = tid >> 2, kq = (tid & 3) * 8;
        const float* s0 = ah + (size_t)(row0 + r) * ld + k0 + kq;
        float4 v0 = *(const float4*)s0;
        float4 v1 = *(const float4*)(s0 + 4);
        *(float4*)&sAh[r * 40 + kq] = v0;
        *(float4*)&sAh[r * 40 + kq + 4] = v1;
        const float* s1 = al + (size_t)(row0 + r) * ld + k0 + kq;
        v0 = *(const float4*)s1;
        v1 = *(const float4*)(s1 + 4);
        *(float4*)&sAl[r * 40 + kq] = v0;
        *(float4*)&sAl[r * 40 + kq + 4] = v1;
      }
      {  // W tile 64x32 (hi+lo), packed rows
        int r = tid >> 1, kq = (tid & 1) * 16;
        const float* s0 = wh + (size_t)r * K + k0 + kq;
        const float* s1 = wl + (size_t)r * K + k0 + kq;
#pragma unroll
        for (int j = 0; j < 4; ++j)
          *(float4*)&sWh[r * 40 + kq + j * 4] = *(const float4*)(s0 + j * 4);
#pragma unroll
        for (int j = 0; j < 4; ++j)
          *(float4*)&sWl[r * 40 + kq + j * 4] = *(const float4*)(s1 + j * 4);
      }
      __syncthreads();
#pragma unroll
      for (int k8 = 0; k8 < 4; ++k8) {
        int aoff = (wm + g) * 40 + k8 * 8 + q * 2;
        float2 ah0 = *(float2*)&sAh[aoff];
        float2 ah1 = *(float2*)&sAh[aoff + 8 * 40];
        float2 al0 = *(float2*)&sAl[aoff];
        float2 al1 = *(float2*)&sAl[aoff + 8 * 40];
        unsigned Ahf[4] = {FB(ah0.x), FB(ah1.x), FB(ah0.y), FB(ah1.y)};
        unsigned Alf[4] = {FB(al0.x), FB(al1.x), FB(al0.y), FB(al1.y)};
#pragma unroll
        for (int nb = 0; nb < 4; ++nb) {
          int boff = (wn + nb * 8 + g) * 40 + k8 * 8 + q * 2;
          float2 bh = *(float2*)&sWh[boff];
          float2 bl = *(float2*)&sWl[boff];
          MMA_TF32(c[nb], Ahf, FB(bh.x), FB(bh.y));   // hi*hi
          MMA_TF32(c[nb], Ahf, FB(bl.x), FB(bl.y));   // hi*lo
          MMA_TF32(c[nb], Alf, FB(bh.x), FB(bh.y));   // lo*hi
        }
      }
    }
  }

  // exchange gates via SMEM
  __syncthreads();
  float* gsm = sm;  // 32 x 65
#pragma unroll
  for (int nb = 0; nb < 4; ++nb) {
    int col = wn + nb * 8 + q * 2;
    gsm[(wm + g) * 65 + col]     = c[nb][0];
    gsm[(wm + g) * 65 + col + 1] = c[nb][1];
    gsm[(wm + g + 8) * 65 + col]     = c[nb][2];
    gsm[(wm + g + 8) * 65 + col + 1] = c[nb][3];
  }
  __syncthreads();

  int hbase = by * 16;
#pragma unroll
  for (int uu = 0; uu < 4; ++uu) {
    int e = tid + uu * 128;          // 512 cells / CTA
    int r = e >> 4, hid = e & 15;
    int gb = row0 + r, gh = hbase + hid;
    float gi = gsm[r * 65 + hid]      + bias[0 * HSZ + gh];
    float gf = gsm[r * 65 + 16 + hid] + bias[1 * HSZ + gh];
    float gg = gsm[r * 65 + 32 + hid] + bias[2 * HSZ + gh];
    float go = gsm[r * 65 + 48 + hid] + bias[3 * HSZ + gh];
    float cold = c_state[gb * HSZ + gh];
    float si = 1.f / (1.f + expf(-gi));
    float sf = 1.f / (1.f + expf(-gf));
    float so = 1.f / (1.f + expf(-go));
    float cn = sf * cold + si * tanhf(gg);
    float hn = so * tanhf(cn);
    c_state[gb * HSZ + gh] = cn;
    float hi, lo;
    tf32_split(hn, hi, lo);
    int shid = ksw(gh);
    out_hi[gb * HSZ + shid] = hi;
    out_lo[gb * HSZ + shid] = lo;
    if (out_f32) out_f32[gb * HSZ + gh] = hn;
  }
}

// ---------------- final projection over all decoder steps ----------------
__global__ __launch_bounds__(256) void out_proj(const float* __restrict__ Wout,
                                                const float* __restrict__ bout,
                                                float* __restrict__ out) {
  __shared__ float hs[32][65];
  __shared__ float wsT[64][36];
  int tid = threadIdx.x;
  int b0 = blockIdx.x * 32;
  int s = blockIdx.y;
  int bloc = tid & 31;
  int f0 = (tid >> 5) * 4;
  float acc[4] = {0.f, 0.f, 0.f, 0.f};
  const float* hsrc = g_h1s + (size_t)s * BSZ * HSZ;

  for (int k0 = 0; k0 < HSZ; k0 += 64) {
    __syncthreads();
#pragma unroll
    for (int qq = 0; qq < 2; ++qq) {
      int idx = tid + qq * 256;
      int row = idx >> 4, kq = idx & 15;
      float4 v = *(const float4*)(hsrc + (size_t)(b0 + row) * HSZ + k0 + kq * 4);
      hs[row][kq * 4 + 0] = v.x; hs[row][kq * 4 + 1] = v.y;
      hs[row][kq * 4 + 2] = v.z; hs[row][kq * 4 + 3] = v.w;
      float4 w = *(const float4*)(Wout + (size_t)row * HSZ + k0 + kq * 4);
      wsT[kq * 4 + 0][row] = w.x; wsT[kq * 4 + 1][row] = w.y;
      wsT[kq * 4 + 2][row] = w.z; wsT[kq * 4 + 3][row] = w.w;
    }
    __syncthreads();
#pragma unroll 8
    for (int kk = 0; kk < 64; ++kk) {
      float hv = hs[bloc][kk];
      float4 w = *(const float4*)&wsT[kk][f0];
      acc[0] += hv * w.x; acc[1] += hv * w.y;
      acc[2] += hv * w.z; acc[3] += hv * w.w;
    }
  }
  float* op = out + (size_t)(b0 + bloc) * TOUT * FSZ + s * FSZ + f0;
  op[0] = acc[0] + bout[f0 + 0];
  op[1] = acc[1] + bout[f0 + 1];
  op[2] = acc[2] + bout[f0 + 2];
  op[3] = acc[3] + bout[f0 + 3];
}

// ---------------- host ----------------
static float* sym_addr(const void* sym) {
  void* p = nullptr;
  cudaGetSymbolAddress(&p, sym);
  return (float*)p;
}

extern "C" void kernel_launch(void* const* d_in, const int* in_sizes, int n_in,
                              void* d_out, int out_size) {
  (void)in_sizes; (void)n_in; (void)out_size;
  const float* x     = (const float*)d_in[0];
  const float* eWih0 = (const float*)d_in[1];
  const float* eWhh0 = (const float*)d_in[2];
  const float* eb0   = (const float*)d_in[3];
  const float* eWih1 = (const float*)d_in[4];
  const float* eWhh1 = (const float*)d_in[5];
  const float* eb1   = (const float*)d_in[6];
  const float* dWih0 = (const float*)d_in[7];
  const float* dWhh0 = (const float*)d_in[8];
  const float* db0   = (const float*)d_in[9];
  const float* dWih1 = (const float*)d_in[10];
  const float* dWhh1 = (const float*)d_in[11];
  const float* db1   = (const float*)d_in[12];
  const float* dWout = (const float*)d_in[13];
  const float* dbout = (const float*)d_in[14];

  float* h0hi = sym_addr(g_h0hi); float* h0lo = sym_addr(g_h0lo);
  float* h1hi = sym_addr(g_h1hi); float* h1lo = sym_addr(g_h1lo);
  float* c0   = sym_addr(g_c0);   float* c1   = sym_addr(g_c1);
  float* xhi  = sym_addr(g_xhi);  float* xlo  = sym_addr(g_xlo);
  float* Wp   = sym_addr(g_Wp);   float* bp   = sym_addr(g_bp);
  float* h1s  = sym_addr(g_h1s);

  float* eWih0h = sym_addr(g_eWih0h); float* eWih0l = sym_addr(g_eWih0l);
  float* eWhh0h = sym_addr(g_eWhh0h); float* eWhh0l = sym_addr(g_eWhh0l);
  float* eWih1h = sym_addr(g_eWih1h); float* eWih1l = sym_addr(g_eWih1l);
  float* eWhh1h = sym_addr(g_eWhh1h); float* eWhh1l = sym_addr(g_eWhh1l);
  float* dWih0h = sym_addr(g_dWih0h); float* dWih0l = sym_addr(g_dWih0l);
  float* dWhh0h = sym_addr(g_dWhh0h); float* dWhh0l = sym_addr(g_dWhh0l);
  float* dWih1h = sym_addr(g_dWih1h); float* dWih1l = sym_addr(g_dWih1l);
  float* dWhh1h = sym_addr(g_dWhh1h); float* dWhh1l = sym_addr(g_dWhh1l);
  float* Wph    = sym_addr(g_Wph);    float* Wpl    = sym_addr(g_Wpl);

  const int pN = BSZ * HSZ;
  const int ldx = TIN * FSZ;
  dim3 grid(BSZ / 32, HSZ / 16);

  zero_init_kernel<<<(BSZ * HSZ) / 256, 256>>>();
  wp_kernel<<<4 * HSZ, 256>>>(dWih0, dWout);
  bp_kernel<<<(4 * HSZ) / 256, 256>>>(dWih0, db0, dbout);
  pack_x<<<(BSZ * TIN * FSZ) / 256, 256>>>(x);
  pack_w<<<(1024 * 32) / 256, 256>>>(eWih0, 32, eWih0h, eWih0l);
  pack_w<<<(1024 * 256) / 256, 256>>>(eWhh0, 256, eWhh0h, eWhh0l);
  pack_w<<<(1024 * 256) / 256, 256>>>(eWih1, 256, eWih1h, eWih1l);
  pack_w<<<(1024 * 256) / 256, 256>>>(eWhh1, 256, eWhh1h, eWhh1l);
  pack_w<<<(1024 * 32) / 256, 256>>>(dWih0, 32, dWih0h, dWih0l);
  pack_w<<<(1024 * 256) / 256, 256>>>(dWhh0, 256, dWhh0h, dWhh0l);
  pack_w<<<(1024 * 256) / 256, 256>>>(dWih1, 256, dWih1h, dWih1l);
  pack_w<<<(1024 * 256) / 256, 256>>>(dWhh1, 256, dWhh1h, dWhh1l);
  pack_w<<<(1024 * 256) / 256, 256>>>(Wp, 256, Wph, Wpl);

  int par = 0;
  // -------- encoder --------
  for (int t = 0; t < TIN; ++t) {
    lstm_step_mma<<<grid, 128>>>(xhi + (size_t)t * FSZ, xlo + (size_t)t * FSZ,
                                 ldx, FSZ, eWih0h, eWih0l,
                                 h0hi + par * pN, h0lo + par * pN,
                                 eWhh0h, eWhh0l, eb0, c0,
                                 h0hi + (par ^ 1) * pN, h0lo + (par ^ 1) * pN,
                                 nullptr);
    lstm_step_mma<<<grid, 128>>>(h0hi + (par ^ 1) * pN, h0lo + (par ^ 1) * pN,
                                 HSZ, HSZ, eWih1h, eWih1l,
                                 h1hi + par * pN, h1lo + par * pN,
                                 eWhh1h, eWhh1l, eb1, c1,
                                 h1hi + (par ^ 1) * pN, h1lo + (par ^ 1) * pN,
                                 nullptr);
    par ^= 1;
  }
  // -------- decoder --------
  for (int s = 0; s < TOUT; ++s) {
    if (s == 0) {
      lstm_step_mma<<<grid, 128>>>(xhi + (size_t)(TIN - 1) * FSZ,
                                   xlo + (size_t)(TIN - 1) * FSZ,
                                   ldx, FSZ, dWih0h, dWih0l,
                                   h0hi + par * pN, h0lo + par * pN,
                                   dWhh0h, dWhh0l, db0, c0,
                                   h0hi + (par ^ 1) * pN, h0lo + (par ^ 1) * pN,
                                   nullptr);
    } else {
      // y = h1@Wout^T + bout folded: W' = Wih0@Wout, b' = b0 + Wih0@bout
      lstm_step_mma<<<grid, 128>>>(h1hi + par * pN, h1lo + par * pN,
                                   HSZ, HSZ, Wph, Wpl,
                                   h0hi + par * pN, h0lo + par * pN,
                                   dWhh0h, dWhh0l, bp, c0,
                                   h0hi + (par ^ 1) * pN, h0lo + (par ^ 1) * pN,
                                   nullptr);
    }
    lstm_step_mma<<<grid, 128>>>(h0hi + (par ^ 1) * pN, h0lo + (par ^ 1) * pN,
                                 HSZ, HSZ, dWih1h, dWih1l,
                                 h1hi + par * pN, h1lo + par * pN,
                                 dWhh1h, dWhh1l, db1, c1,
                                 h1hi + (par ^ 1) * pN, h1lo + (par ^ 1) * pN,
                                 h1s + (size_t)s * pN);
    par ^= 1;
  }
  // -------- output projection for all 96 steps --------
  out_proj<<<dim3(BSZ / 32, TOUT), 256>>>(dWout, dbout, (float*)d_out);
}

// round 8
// speedup vs baseline: 1.0024x; 1.0024x over previous
#include <cuda_runtime.h>
#include <math.h>

#define BSZ 256
#define HSZ 256
#define TIN 336
#define TOUT 96
#define FSZ 32

// ---------------- device-global scratch (allocation-free) ----------------
// activations stored as (hi, lo) tf32 split, feature-index swizzled
__device__ float g_h0hi[2][BSZ * HSZ], g_h0lo[2][BSZ * HSZ];
__device__ float g_h1hi[2][BSZ * HSZ], g_h1lo[2][BSZ * HSZ];
__device__ float g_c0[BSZ * HSZ], g_c1[BSZ * HSZ];
__device__ float g_xhi[BSZ * TIN * FSZ], g_xlo[BSZ * TIN * FSZ];
__device__ float g_Wp[4 * HSZ * HSZ];   // dec_Wih0 @ dec_Wout (fp32, pre-pack)
__device__ float g_bp[4 * HSZ];         // dec_b0 + dec_Wih0 @ dec_bout
__device__ float g_h1s[(size_t)TOUT * BSZ * HSZ]; // decoder h1 per step (fp32)

// packed+swizzled hi/lo weights: layout [1024 packed rows][K]
__device__ float g_eWih0h[1024 * 32],  g_eWih0l[1024 * 32];
__device__ float g_eWhh0h[1024 * 256], g_eWhh0l[1024 * 256];
__device__ float g_eWih1h[1024 * 256], g_eWih1l[1024 * 256];
__device__ float g_eWhh1h[1024 * 256], g_eWhh1l[1024 * 256];
__device__ float g_dWih0h[1024 * 32],  g_dWih0l[1024 * 32];
__device__ float g_dWhh0h[1024 * 256], g_dWhh0l[1024 * 256];
__device__ float g_dWih1h[1024 * 256], g_dWih1l[1024 * 256];
__device__ float g_dWhh1h[1024 * 256], g_dWhh1l[1024 * 256];
__device__ float g_Wph[1024 * 256],    g_Wpl[1024 * 256];

// ---------------- helpers ----------------
__device__ __forceinline__ unsigned f2tf32(float v) {
  unsigned r;
  asm("cvt.rna.tf32.f32 %0, %1;" : "=r"(r) : "f"(v));
  return r;
}
__device__ __forceinline__ void tf32_split(float v, float& hi, float& lo) {
  unsigned hb = f2tf32(v);
  hi = __uint_as_float(hb);
  float l = v - hi;
  lo = __uint_as_float(f2tf32(l));
}
// swizzle within 8-group so that (k, k+4) land adjacent: perm(kin)=(kin&3)*2+(kin>>2)
__device__ __forceinline__ int ksw(int k) {
  return (k & ~7) | (((k & 3) << 1) | ((k >> 2) & 1));
}
// inverse: given swizzled pos c, original kin
__device__ __forceinline__ int kunsw(int c) {
  return (c & ~7) | (((c & 1) << 2) | ((c & 7) >> 1));
}

#define FB(x) __float_as_uint(x)
#define MMA_TF32(C, A, B0, B1)                                              \
  asm volatile(                                                             \
      "mma.sync.aligned.m16n8k8.row.col.f32.tf32.tf32.f32 "                 \
      "{%0,%1,%2,%3},{%4,%5,%6,%7},{%8,%9},{%0,%1,%2,%3};"                  \
      : "+f"(C[0]), "+f"(C[1]), "+f"(C[2]), "+f"(C[3])                      \
      : "r"(A[0]), "r"(A[1]), "r"(A[2]), "r"(A[3]), "r"(B0), "r"(B1))

// ---------------- init / preprocess kernels ----------------
__global__ void zero_init_kernel() {
  int i = blockIdx.x * blockDim.x + threadIdx.x;
  g_h0hi[0][i] = 0.f; g_h0lo[0][i] = 0.f;
  g_h1hi[0][i] = 0.f; g_h1lo[0][i] = 0.f;
  g_c0[i] = 0.f; g_c1[i] = 0.f;
}

__global__ void wp_kernel(const float* __restrict__ Wih0,
                          const float* __restrict__ Wout) {
  __shared__ float wr[FSZ];
  int c = blockIdx.x;                    // gate row 0..1023
  if (threadIdx.x < FSZ) wr[threadIdx.x] = Wih0[c * FSZ + threadIdx.x];
  __syncthreads();
  int k = threadIdx.x;                   // hidden col 0..255
  float acc = 0.f;
#pragma unroll
  for (int f = 0; f < FSZ; ++f) acc += wr[f] * Wout[f * HSZ + k];
  g_Wp[c * HSZ + k] = acc;
}

__global__ void bp_kernel(const float* __restrict__ Wih0,
                          const float* __restrict__ b0,
                          const float* __restrict__ bout) {
  int c = blockIdx.x * blockDim.x + threadIdx.x;
  float acc = b0[c];
#pragma unroll
  for (int f = 0; f < FSZ; ++f) acc += Wih0[c * FSZ + f] * bout[f];
  g_bp[c] = acc;
}

// pack weights: out[pr][c] (pr = by*64 + n; orig row r = (n>>4)*256 + by*16 + (n&15);
// orig col = kunsw(c)); split into tf32 hi/lo
__global__ void pack_w(const float* __restrict__ W, int K,
                       float* __restrict__ ohi, float* __restrict__ olo) {
  int idx = blockIdx.x * 256 + threadIdx.x;
  if (idx >= 1024 * K) return;
  int pr = idx / K, c = idx % K;
  int n = pr & 63, by = pr >> 6;
  int r = (n >> 4) * 256 + by * 16 + (n & 15);
  float v = W[r * K + kunsw(c)];
  float hi, lo;
  tf32_split(v, hi, lo);
  ohi[idx] = hi; olo[idx] = lo;
}

__global__ void pack_x(const float* __restrict__ x) {
  int idx = blockIdx.x * 256 + threadIdx.x;  // BSZ*TIN*FSZ = 2752512
  int c = idx & 31, base = idx & ~31;
  float v = x[base + kunsw(c)];
  float hi, lo;
  tf32_split(v, hi, lo);
  g_xhi[idx] = hi; g_xlo[idx] = lo;
}

// ---------------- fused LSTM cell step (tf32x3 MMA) ----------------
// gates[B,4H] = A[B,D]@Wih^T + hin[B,H]@Whh^T + bias;  then pointwise.
// CTA: 128 threads (4 warps), tile 32 batch x 64 gate-cols.
// Warps 2x2: wm=(wid&1)*16, wn=(wid>>1)*32.  Grid (8,16)=128 CTAs.
__global__ __launch_bounds__(128) void lstm_step_mma(
    const float* __restrict__ Ahi, const float* __restrict__ Alo, int lda, int D,
    const float* __restrict__ Wih_hi, const float* __restrict__ Wih_lo,
    const float* __restrict__ hin_hi, const float* __restrict__ hin_lo,
    const float* __restrict__ Whh_hi, const float* __restrict__ Whh_lo,
    const float* __restrict__ bias,
    float* __restrict__ c_state,
    float* __restrict__ out_hi, float* __restrict__ out_lo,
    float* __restrict__ out_f32) {
  // sAh [0,1280) sAl [1280,2560) sWh [2560,5120) sWl [5120,7680)  (pitch 40)
  __shared__ __align__(16) float sm[7680];
  float* sAh = sm;
  float* sAl = sm + 1280;
  float* sWh = sm + 2560;
  float* sWl = sm + 5120;

  int tid = threadIdx.x;
  int row0 = blockIdx.x * 32;
  int by = blockIdx.y;
  int lane = tid & 31, wid = tid >> 5;
  int g = lane >> 2, q = lane & 3;
  int wm = (wid & 1) * 16, wn = (wid >> 1) * 32;
  float c[4][4] = {};

  for (int seg = 0; seg < 2; ++seg) {
    const float* ah = seg ? hin_hi : Ahi;
    const float* al = seg ? hin_lo : Alo;
    int ld = seg ? HSZ : lda;
    int K = seg ? HSZ : D;
    const float* wh = (seg ? Whh_hi : Wih_hi) + (size_t)by * 64 * K;
    const float* wl = (seg ? Whh_lo : Wih_lo) + (size_t)by * 64 * K;

    for (int k0 = 0; k0 < K; k0 += 32) {
      __syncthreads();
      {  // A tile 32x32 (hi+lo), already swizzled in global
        int r = tid >> 2, kq = (tid & 3) * 8;
        const float* s0 = ah + (size_t)(row0 + r) * ld + k0 + kq;
        float4 v0 = *(const float4*)s0;
        float4 v1 = *(const float4*)(s0 + 4);
        *(float4*)&sAh[r * 40 + kq] = v0;
        *(float4*)&sAh[r * 40 + kq + 4] = v1;
        const float* s1 = al + (size_t)(row0 + r) * ld + k0 + kq;
        v0 = *(const float4*)s1;
        v1 = *(const float4*)(s1 + 4);
        *(float4*)&sAl[r * 40 + kq] = v0;
        *(float4*)&sAl[r * 40 + kq + 4] = v1;
      }
      {  // W tile 64x32 (hi+lo), packed rows
        int r = tid >> 1, kq = (tid & 1) * 16;
        const float* s0 = wh + (size_t)r * K + k0 + kq;
        const float* s1 = wl + (size_t)r * K + k0 + kq;
#pragma unroll
        for (int j = 0; j < 4; ++j)
          *(float4*)&sWh[r * 40 + kq + j * 4] = *(const float4*)(s0 + j * 4);
#pragma unroll
        for (int j = 0; j < 4; ++j)
          *(float4*)&sWl[r * 40 + kq + j * 4] = *(const float4*)(s1 + j * 4);
      }
      __syncthreads();
#pragma unroll
      for (int k8 = 0; k8 < 4; ++k8) {
        int aoff = (wm + g) * 40 + k8 * 8 + q * 2;
        float2 ah0 = *(float2*)&sAh[aoff];
        float2 ah1 = *(float2*)&sAh[aoff + 8 * 40];
        float2 al0 = *(float2*)&sAl[aoff];
        float2 al1 = *(float2*)&sAl[aoff + 8 * 40];
        unsigned Ahf[4] = {FB(ah0.x), FB(ah1.x), FB(ah0.y), FB(ah1.y)};
        unsigned Alf[4] = {FB(al0.x), FB(al1.x), FB(al0.y), FB(al1.y)};
#pragma unroll
        for (int nb = 0; nb < 4; ++nb) {
          int boff = (wn + nb * 8 + g) * 40 + k8 * 8 + q * 2;
          float2 bh = *(float2*)&sWh[boff];
          float2 bl = *(float2*)&sWl[boff];
          MMA_TF32(c[nb], Ahf, FB(bh.x), FB(bh.y));   // hi*hi
          MMA_TF32(c[nb], Ahf, FB(bl.x), FB(bl.y));   // hi*lo
          MMA_TF32(c[nb], Alf, FB(bh.x), FB(bh.y));   // lo*hi
        }
      }
    }
  }

  // exchange gates via SMEM
  __syncthreads();
  float* gsm = sm;  // 32 x 65
#pragma unroll
  for (int nb = 0; nb < 4; ++nb) {
    int col = wn + nb * 8 + q * 2;
    gsm[(wm + g) * 65 + col]     = c[nb][0];
    gsm[(wm + g) * 65 + col + 1] = c[nb][1];
    gsm[(wm + g + 8) * 65 + col]     = c[nb][2];
    gsm[(wm + g + 8) * 65 + col + 1] = c[nb][3];
  }
  __syncthreads();

  int hbase = by * 16;
#pragma unroll
  for (int uu = 0; uu < 4; ++uu) {
    int e = tid + uu * 128;          // 512 cells / CTA
    int r = e >> 4, hid = e & 15;
    int gb = row0 + r, gh = hbase + hid;
    float gi = gsm[r * 65 + hid]      + bias[0 * HSZ + gh];
    float gf = gsm[r * 65 + 16 + hid] + bias[1 * HSZ + gh];
    float gg = gsm[r * 65 + 32 + hid] + bias[2 * HSZ + gh];
    float go = gsm[r * 65 + 48 + hid] + bias[3 * HSZ + gh];
    float cold = c_state[gb * HSZ + gh];
    float si = 1.f / (1.f + expf(-gi));
    float sf = 1.f / (1.f + expf(-gf));
    float so = 1.f / (1.f + expf(-go));
    float cn = sf * cold + si * tanhf(gg);
    float hn = so * tanhf(cn);
    c_state[gb * HSZ + gh] = cn;
    float hi, lo;
    tf32_split(hn, hi, lo);
    int shid = ksw(gh);
    out_hi[gb * HSZ + shid] = hi;
    out_lo[gb * HSZ + shid] = lo;
    if (out_f32) out_f32[gb * HSZ + gh] = hn;
  }
}

// ---------------- final projection over all decoder steps ----------------
__global__ __launch_bounds__(256) void out_proj(const float* __restrict__ Wout,
                                                const float* __restrict__ bout,
                                                float* __restrict__ out) {
  __shared__ float hs[32][65];
  __shared__ float wsT[64][36];
  int tid = threadIdx.x;
  int b0 = blockIdx.x * 32;
  int s = blockIdx.y;
  int bloc = tid & 31;
  int f0 = (tid >> 5) * 4;
  float acc[4] = {0.f, 0.f, 0.f, 0.f};
  const float* hsrc = g_h1s + (size_t)s * BSZ * HSZ;

  for (int k0 = 0; k0 < HSZ; k0 += 64) {
    __syncthreads();
#pragma unroll
    for (int qq = 0; qq < 2; ++qq) {
      int idx = tid + qq * 256;
      int row = idx >> 4, kq = idx & 15;
      float4 v = *(const float4*)(hsrc + (size_t)(b0 + row) * HSZ + k0 + kq * 4);
      hs[row][kq * 4 + 0] = v.x; hs[row][kq * 4 + 1] = v.y;
      hs[row][kq * 4 + 2] = v.z; hs[row][kq * 4 + 3] = v.w;
      float4 w = *(const float4*)(Wout + (size_t)row * HSZ + k0 + kq * 4);
      wsT[kq * 4 + 0][row] = w.x; wsT[kq * 4 + 1][row] = w.y;
      wsT[kq * 4 + 2][row] = w.z; wsT[kq * 4 + 3][row] = w.w;
    }
    __syncthreads();
#pragma unroll 8
    for (int kk = 0; kk < 64; ++kk) {
      float hv = hs[bloc][kk];
      float4 w = *(const float4*)&wsT[kk][f0];
      acc[0] += hv * w.x; acc[1] += hv * w.y;
      acc[2] += hv * w.z; acc[3] += hv * w.w;
    }
  }
  float* op = out + (size_t)(b0 + bloc) * TOUT * FSZ + s * FSZ + f0;
  op[0] = acc[0] + bout[f0 + 0];
  op[1] = acc[1] + bout[f0 + 1];
  op[2] = acc[2] + bout[f0 + 2];
  op[3] = acc[3] + bout[f0 + 3];
}

// ---------------- host ----------------
static float* sym_addr(const void* sym) {
  void* p = nullptr;
  cudaGetSymbolAddress(&p, sym);
  return (float*)p;
}

extern "C" void kernel_launch(void* const* d_in, const int* in_sizes, int n_in,
                              void* d_out, int out_size) {
  (void)in_sizes; (void)n_in; (void)out_size;
  const float* x     = (const float*)d_in[0];
  const float* eWih0 = (const float*)d_in[1];
  const float* eWhh0 = (const float*)d_in[2];
  const float* eb0   = (const float*)d_in[3];
  const float* eWih1 = (const float*)d_in[4];
  const float* eWhh1 = (const float*)d_in[5];
  const float* eb1   = (const float*)d_in[6];
  const float* dWih0 = (const float*)d_in[7];
  const float* dWhh0 = (const float*)d_in[8];
  const float* db0   = (const float*)d_in[9];
  const float* dWih1 = (const float*)d_in[10];
  const float* dWhh1 = (const float*)d_in[11];
  const float* db1   = (const float*)d_in[12];
  const float* dWout = (const float*)d_in[13];
  const float* dbout = (const float*)d_in[14];

  float* h0hi = sym_addr(g_h0hi); float* h0lo = sym_addr(g_h0lo);
  float* h1hi = sym_addr(g_h1hi); float* h1lo = sym_addr(g_h1lo);
  float* c0   = sym_addr(g_c0);   float* c1   = sym_addr(g_c1);
  float* xhi  = sym_addr(g_xhi);  float* xlo  = sym_addr(g_xlo);
  float* Wp   = sym_addr(g_Wp);   float* bp   = sym_addr(g_bp);
  float* h1s  = sym_addr(g_h1s);

  float* eWih0h = sym_addr(g_eWih0h); float* eWih0l = sym_addr(g_eWih0l);
  float* eWhh0h = sym_addr(g_eWhh0h); float* eWhh0l = sym_addr(g_eWhh0l);
  float* eWih1h = sym_addr(g_eWih1h); float* eWih1l = sym_addr(g_eWih1l);
  float* eWhh1h = sym_addr(g_eWhh1h); float* eWhh1l = sym_addr(g_eWhh1l);
  float* dWih0h = sym_addr(g_dWih0h); float* dWih0l = sym_addr(g_dWih0l);
  float* dWhh0h = sym_addr(g_dWhh0h); float* dWhh0l = sym_addr(g_dWhh0l);
  float* dWih1h = sym_addr(g_dWih1h); float* dWih1l = sym_addr(g_dWih1l);
  float* dWhh1h = sym_addr(g_dWhh1h); float* dWhh1l = sym_addr(g_dWhh1l);
  float* Wph    = sym_addr(g_Wph);    float* Wpl    = sym_addr(g_Wpl);

  const int pN = BSZ * HSZ;
  const int ldx = TIN * FSZ;
  dim3 grid(BSZ / 32, HSZ / 16);

  zero_init_kernel<<<(BSZ * HSZ) / 256, 256>>>();
  wp_kernel<<<4 * HSZ, 256>>>(dWih0, dWout);
  bp_kernel<<<(4 * HSZ) / 256, 256>>>(dWih0, db0, dbout);
  pack_x<<<(BSZ * TIN * FSZ) / 256, 256>>>(x);
  pack_w<<<(1024 * 32) / 256, 256>>>(eWih0, 32, eWih0h, eWih0l);
  pack_w<<<(1024 * 256) / 256, 256>>>(eWhh0, 256, eWhh0h, eWhh0l);
  pack_w<<<(1024 * 256) / 256, 256>>>(eWih1, 256, eWih1h, eWih1l);
  pack_w<<<(1024 * 256) / 256, 256>>>(eWhh1, 256, eWhh1h, eWhh1l);
  pack_w<<<(1024 * 32) / 256, 256>>>(dWih0, 32, dWih0h, dWih0l);
  pack_w<<<(1024 * 256) / 256, 256>>>(dWhh0, 256, dWhh0h, dWhh0l);
  pack_w<<<(1024 * 256) / 256, 256>>>(dWih1, 256, dWih1h, dWih1l);
  pack_w<<<(1024 * 256) / 256, 256>>>(dWhh1, 256, dWhh1h, dWhh1l);
  pack_w<<<(1024 * 256) / 256, 256>>>(Wp, 256, Wph, Wpl);

  int par = 0;
  // -------- encoder --------
  for (int t = 0; t < TIN; ++t) {
    lstm_step_mma<<<grid, 128>>>(xhi + (size_t)t * FSZ, xlo + (size_t)t * FSZ,
                                 ldx, FSZ, eWih0h, eWih0l,
                                 h0hi + par * pN, h0lo + par * pN,
                                 eWhh0h, eWhh0l, eb0, c0,
                                 h0hi + (par ^ 1) * pN, h0lo + (par ^ 1) * pN,
                                 nullptr);
    lstm_step_mma<<<grid, 128>>>(h0hi + (par ^ 1) * pN, h0lo + (par ^ 1) * pN,
                                 HSZ, HSZ, eWih1h, eWih1l,
                                 h1hi + par * pN, h1lo + par * pN,
                                 eWhh1h, eWhh1l, eb1, c1,
                                 h1hi + (par ^ 1) * pN, h1lo + (par ^ 1) * pN,
                                 nullptr);
    par ^= 1;
  }
  // -------- decoder --------
  for (int s = 0; s < TOUT; ++s) {
    if (s == 0) {
      lstm_step_mma<<<grid, 128>>>(xhi + (size_t)(TIN - 1) * FSZ,
                                   xlo + (size_t)(TIN - 1) * FSZ,
                                   ldx, FSZ, dWih0h, dWih0l,
                                   h0hi + par * pN, h0lo + par * pN,
                                   dWhh0h, dWhh0l, db0, c0,
                                   h0hi + (par ^ 1) * pN, h0lo + (par ^ 1) * pN,
                                   nullptr);
    } else {
      // y = h1@Wout^T + bout folded: W' = Wih0@Wout, b' = b0 + Wih0@bout
      lstm_step_mma<<<grid, 128>>>(h1hi + par * pN, h1lo + par * pN,
                                   HSZ, HSZ, Wph, Wpl,
                                   h0hi + par * pN, h0lo + par * pN,
                                   dWhh0h, dWhh0l, bp, c0,
                                   h0hi + (par ^ 1) * pN, h0lo + (par ^ 1) * pN,
                                   nullptr);
    }
    lstm_step_mma<<<grid, 128>>>(h0hi + (par ^ 1) * pN, h0lo + (par ^ 1) * pN,
                                 HSZ, HSZ, dWih1h, dWih1l,
                                 h1hi + par * pN, h1lo + par * pN,
                                 dWhh1h, dWhh1l, db1, c1,
                                 h1hi + (par ^ 1) * pN, h1lo + (par ^ 1) * pN,
                                 h1s + (size_t)s * pN);
    par ^= 1;
  }
  // -------- output projection for all 96 steps --------
  out_proj<<<dim3(BSZ / 32, TOUT), 256>>>(dWout, dbout, (float*)d_out);
}

// round 9
// speedup vs baseline: 1.5451x; 1.5415x over previous
#include <cuda_runtime.h>
#include <cuda_bf16.h>
#include <math.h>
#include <stdint.h>

#define BSZ 256
#define HSZ 256
#define TIN 336
#define TOUT 96
#define FSZ 32
#define PH 128   // packed uint32 words per h row (256 bf16 pairs / 2)
#define PX 16    // packed words per (b,t) of x

// ---------------- device-global scratch (allocation-free) ----------------
__device__ uint32_t g_h0hi[2][BSZ * PH], g_h0lo[2][BSZ * PH];
__device__ uint32_t g_h1hi[2][BSZ * PH], g_h1lo[2][BSZ * PH];
__device__ float g_c0[BSZ * HSZ], g_c1[BSZ * HSZ];
__device__ uint32_t g_xhi[BSZ * TIN * PX], g_xlo[BSZ * TIN * PX];
__device__ float g_Wp[4 * HSZ * HSZ];
__device__ float g_bp[4 * HSZ];
__device__ float g_h1s[(size_t)TOUT * BSZ * HSZ];

// packed bf16 hi/lo weights: [1024 packed rows][K/2 words]
__device__ uint32_t g_eWih0h[1024 * 16],  g_eWih0l[1024 * 16];
__device__ uint32_t g_eWhh0h[1024 * 128], g_eWhh0l[1024 * 128];
__device__ uint32_t g_eWih1h[1024 * 128], g_eWih1l[1024 * 128];
__device__ uint32_t g_eWhh1h[1024 * 128], g_eWhh1l[1024 * 128];
__device__ uint32_t g_dWih0h[1024 * 16],  g_dWih0l[1024 * 16];
__device__ uint32_t g_dWhh0h[1024 * 128], g_dWhh0l[1024 * 128];
__device__ uint32_t g_dWih1h[1024 * 128], g_dWih1l[1024 * 128];
__device__ uint32_t g_dWhh1h[1024 * 128], g_dWhh1l[1024 * 128];
__device__ uint32_t g_Wph[1024 * 128],    g_Wpl[1024 * 128];

// ---------------- helpers ----------------
// word j (0..7) within a k16 chunk holds pair lp = ((j&1)<<2)|(j>>1),
// i.e. pairs (q, q+4) sit at words (2q, 2q+1) -> one LDS.64 per fragment piece.
__device__ __forceinline__ int j2lp(int j) { return ((j & 1) << 2) | (j >> 1); }

__device__ __forceinline__ void split2(float v0, float v1, uint32_t& hi,
                                       uint32_t& lo) {
  __nv_bfloat16 h0 = __float2bfloat16_rn(v0);
  __nv_bfloat16 h1 = __float2bfloat16_rn(v1);
  __nv_bfloat16 l0 = __float2bfloat16_rn(v0 - __bfloat162float(h0));
  __nv_bfloat16 l1 = __float2bfloat16_rn(v1 - __bfloat162float(h1));
  __nv_bfloat162 ph = __nv_bfloat162(h0, h1);
  __nv_bfloat162 pl = __nv_bfloat162(l0, l1);
  hi = *(uint32_t*)&ph;
  lo = *(uint32_t*)&pl;
}

#define MMA_BF16(C, a0, a1, a2, a3, b0, b1)                                   \
  asm volatile(                                                               \
      "mma.sync.aligned.m16n8k16.row.col.f32.bf16.bf16.f32 "                  \
      "{%0,%1,%2,%3},{%4,%5,%6,%7},{%8,%9},{%0,%1,%2,%3};"                    \
      : "+f"(C[0]), "+f"(C[1]), "+f"(C[2]), "+f"(C[3])                        \
      : "r"(a0), "r"(a1), "r"(a2), "r"(a3), "r"(b0), "r"(b1))

// ---------------- init / preprocess ----------------
__global__ void zero_init_kernel() {
  int i = blockIdx.x * blockDim.x + threadIdx.x;   // 65536 threads
  g_c0[i] = 0.f;
  g_c1[i] = 0.f;
  if (i < BSZ * PH) {
    g_h0hi[0][i] = 0u; g_h0hi[1][i] = 0u; g_h0lo[0][i] = 0u; g_h0lo[1][i] = 0u;
    g_h1hi[0][i] = 0u; g_h1hi[1][i] = 0u; g_h1lo[0][i] = 0u; g_h1lo[1][i] = 0u;
  }
}

__global__ void wp_kernel(const float* __restrict__ Wih0,
                          const float* __restrict__ Wout) {
  __shared__ float wr[FSZ];
  int c = blockIdx.x;
  if (threadIdx.x < FSZ) wr[threadIdx.x] = Wih0[c * FSZ + threadIdx.x];
  __syncthreads();
  int k = threadIdx.x;
  float acc = 0.f;
#pragma unroll
  for (int f = 0; f < FSZ; ++f) acc += wr[f] * Wout[f * HSZ + k];
  g_Wp[c * HSZ + k] = acc;
}

__global__ void bp_kernel(const float* __restrict__ Wih0,
                          const float* __restrict__ b0,
                          const float* __restrict__ bout) {
  int c = blockIdx.x * blockDim.x + threadIdx.x;
  float acc = b0[c];
#pragma unroll
  for (int f = 0; f < FSZ; ++f) acc += Wih0[c * FSZ + f] * bout[f];
  g_bp[c] = acc;
}

// pack fp32 W[1024][K] -> packed-row bf16 hi/lo planes [1024][K/2]
__global__ void pack_w(const float* __restrict__ W, int K,
                       uint32_t* __restrict__ ohi, uint32_t* __restrict__ olo) {
  int P = K >> 1;
  int idx = blockIdx.x * 256 + threadIdx.x;
  if (idx >= 1024 * P) return;
  int pr = idx / P, w = idx % P;
  int n = pr & 63, by = pr >> 6;
  int r = (n >> 4) * 256 + by * 16 + (n & 15);
  int cch = w >> 3, j = w & 7;
  int k0 = cch * 16 + 2 * j2lp(j);
  split2(W[r * K + k0], W[r * K + k0 + 1], ohi[idx], olo[idx]);
}

__global__ void pack_x(const float* __restrict__ x) {
  int idx = blockIdx.x * 256 + threadIdx.x;   // BSZ*TIN*PX
  int w = idx & (PX - 1);
  int bt = idx >> 4;                          // b*TIN + t
  int cch = w >> 3, j = w & 7;
  int k0 = cch * 16 + 2 * j2lp(j);
  const float* src = x + (size_t)bt * FSZ + k0;
  split2(src[0], src[1], g_xhi[idx], g_xlo[idx]);
}

// ---------------- fused LSTM cell step (bf16x3 mma, pipelined) ----------------
// gates[B,4H] = A[B,2*Pa]@Wih^T + h[B,256]@Whh^T + bias, then pointwise.
// 256 threads, 8 warps (2x4), CTA tile 32 batch x 64 gate-cols, grid (8,16).
__global__ __launch_bounds__(256) void lstm_step(
    const uint32_t* __restrict__ Ahi, const uint32_t* __restrict__ Alo,
    int ldaA, int Pa,
    const uint32_t* __restrict__ W0h, const uint32_t* __restrict__ W0l,
    const uint32_t* __restrict__ Hhi, const uint32_t* __restrict__ Hlo,
    const uint32_t* __restrict__ W1h, const uint32_t* __restrict__ W1l,
    const float* __restrict__ bias, float* __restrict__ c_state,
    uint32_t* __restrict__ outHi, uint32_t* __restrict__ outLo,
    float* __restrict__ outF) {
  // buffers: per buf 1536 words: sAh 256 | sAl 256 | sWh 512 | sWl 512
  __shared__ __align__(16) uint32_t sm[3072];
  int tid = threadIdx.x;
  int row0 = blockIdx.x * 32;
  int by = blockIdx.y;
  int lane = tid & 31, wid = tid >> 5;
  int g = lane >> 2, q = lane & 3;
  int wm = (wid & 1) * 16, wn = (wid >> 1) * 16;

  W0h += (size_t)by * 64 * Pa;  W0l += (size_t)by * 64 * Pa;
  W1h += (size_t)by * 64 * PH;  W1l += (size_t)by * 64 * PH;

  float c[2][4] = {};
  int c0 = Pa >> 3;
  int N = c0 + 16;

  int ra = tid >> 3, j = tid & 7;   // A fill: row ra, word j
  int rw = tid >> 3;                // W fill: rows rw and rw+32, word j

  uint32_t rAh, rAl, rWh0, rWh1, rWl0, rWl1;
  // prefetch chunk 0 (seg 0 always exists)
  {
    rAh = Ahi[(size_t)(row0 + ra) * ldaA + j];
    rAl = Alo[(size_t)(row0 + ra) * ldaA + j];
    rWh0 = W0h[(size_t)rw * Pa + j];        rWh1 = W0h[(size_t)(rw + 32) * Pa + j];
    rWl0 = W0l[(size_t)rw * Pa + j];        rWl1 = W0l[(size_t)(rw + 32) * Pa + j];
  }
  uint32_t* sAh = sm;        uint32_t* sAl = sm + 256;
  uint32_t* sWh = sm + 512;  uint32_t* sWl = sm + 1024;
  // store chunk 0 into buf0
  sAh[ra * 8 + j] = rAh;  sAl[ra * 8 + j] = rAl;
  sWh[rw * 8 + j] = rWh0; sWh[(rw + 32) * 8 + j] = rWh1;
  sWl[rw * 8 + j] = rWl0; sWl[(rw + 32) * 8 + j] = rWl1;
  __syncthreads();

  for (int i = 0; i < N; ++i) {
    int buf = (i & 1) * 1536;
    if (i + 1 < N) {  // prefetch next chunk
      int ii = i + 1;
      if (ii < c0) {
        int off = ii * 8 + j;
        rAh = Ahi[(size_t)(row0 + ra) * ldaA + off];
        rAl = Alo[(size_t)(row0 + ra) * ldaA + off];
        rWh0 = W0h[(size_t)rw * Pa + off];  rWh1 = W0h[(size_t)(rw + 32) * Pa + off];
        rWl0 = W0l[(size_t)rw * Pa + off];  rWl1 = W0l[(size_t)(rw + 32) * Pa + off];
      } else {
        int off = (ii - c0) * 8 + j;
        rAh = Hhi[(size_t)(row0 + ra) * PH + off];
        rAl = Hlo[(size_t)(row0 + ra) * PH + off];
        rWh0 = W1h[(size_t)rw * PH + off];  rWh1 = W1h[(size_t)(rw + 32) * PH + off];
        rWl0 = W1l[(size_t)rw * PH + off];  rWl1 = W1l[(size_t)(rw + 32) * PH + off];
      }
    }
    // MMA on current buffer
    {
      const uint32_t* bAh = sm + buf;
      const uint32_t* bAl = sm + buf + 256;
      const uint32_t* bWh = sm + buf + 512;
      const uint32_t* bWl = sm + buf + 1024;
      int aoff = (wm + g) * 8 + 2 * q;
      uint2 Ah0 = *(const uint2*)&bAh[aoff];
      uint2 Ah1 = *(const uint2*)&bAh[aoff + 64];
      uint2 Al0 = *(const uint2*)&bAl[aoff];
      uint2 Al1 = *(const uint2*)&bAl[aoff + 64];
#pragma unroll
      for (int nb = 0; nb < 2; ++nb) {
        int boff = (wn + nb * 8 + g) * 8 + 2 * q;
        uint2 Bh = *(const uint2*)&bWh[boff];
        uint2 Bl = *(const uint2*)&bWl[boff];
        MMA_BF16(c[nb], Ah0.x, Ah1.x, Ah0.y, Ah1.y, Bh.x, Bh.y);
        MMA_BF16(c[nb], Ah0.x, Ah1.x, Ah0.y, Ah1.y, Bl.x, Bl.y);
        MMA_BF16(c[nb], Al0.x, Al1.x, Al0.y, Al1.y, Bh.x, Bh.y);
      }
    }
    if (i + 1 < N) {  // store prefetched chunk into other buffer
      int nbuf = ((i + 1) & 1) * 1536;
      uint32_t* nAh = sm + nbuf;
      uint32_t* nAl = sm + nbuf + 256;
      uint32_t* nWh = sm + nbuf + 512;
      uint32_t* nWl = sm + nbuf + 1024;
      nAh[ra * 8 + j] = rAh;  nAl[ra * 8 + j] = rAl;
      nWh[rw * 8 + j] = rWh0; nWh[(rw + 32) * 8 + j] = rWh1;
      nWl[rw * 8 + j] = rWl0; nWl[(rw + 32) * 8 + j] = rWl1;
      __syncthreads();
    }
  }
  __syncthreads();

  // ---- exchange gates via SMEM (reuse sm as float) ----
  float* gsm = (float*)sm;  // 32 x 65
#pragma unroll
  for (int nb = 0; nb < 2; ++nb) {
    int col = wn + nb * 8 + 2 * q;
    gsm[(wm + g) * 65 + col]     = c[nb][0];
    gsm[(wm + g) * 65 + col + 1] = c[nb][1];
    gsm[(wm + g + 8) * 65 + col]     = c[nb][2];
    gsm[(wm + g + 8) * 65 + col + 1] = c[nb][3];
  }
  __syncthreads();

  float* hbuf = (float*)sm + 2112;  // 32 x 17
  int hbase = by * 16;
#pragma unroll
  for (int uu = 0; uu < 2; ++uu) {
    int e = tid + uu * 256;
    int r = e >> 4, hid = e & 15;
    int gb = row0 + r, gh = hbase + hid;
    float gi = gsm[r * 65 + hid]      + bias[0 * HSZ + gh];
    float gf = gsm[r * 65 + 16 + hid] + bias[1 * HSZ + gh];
    float gg = gsm[r * 65 + 32 + hid] + bias[2 * HSZ + gh];
    float go = gsm[r * 65 + 48 + hid] + bias[3 * HSZ + gh];
    float cold = c_state[gb * HSZ + gh];
    float si = 1.f / (1.f + expf(-gi));
    float sf = 1.f / (1.f + expf(-gf));
    float so = 1.f / (1.f + expf(-go));
    float cn = sf * cold + si * tanhf(gg);
    float hn = so * tanhf(cn);
    c_state[gb * HSZ + gh] = cn;
    hbuf[r * 17 + hid] = hn;
    if (outF) outF[gb * HSZ + gh] = hn;
  }
  __syncthreads();

  // ---- pack h -> bf16 hi/lo words (swizzled pair layout) ----
  {
    int row = tid >> 3, jj = tid & 7;
    int lp = j2lp(jj);
    float v0 = hbuf[row * 17 + 2 * lp];
    float v1 = hbuf[row * 17 + 2 * lp + 1];
    uint32_t hi, lo;
    split2(v0, v1, hi, lo);
    size_t oidx = (size_t)(row0 + row) * PH + by * 8 + jj;
    outHi[oidx] = hi;
    outLo[oidx] = lo;
  }
}

// ---------------- final projection over all decoder steps ----------------
__global__ __launch_bounds__(256) void out_proj(const float* __restrict__ Wout,
                                                const float* __restrict__ bout,
                                                float* __restrict__ out) {
  __shared__ float hs[32][65];
  __shared__ float wsT[64][36];
  int tid = threadIdx.x;
  int b0 = blockIdx.x * 32;
  int s = blockIdx.y;
  int bloc = tid & 31;
  int f0 = (tid >> 5) * 4;
  float acc[4] = {0.f, 0.f, 0.f, 0.f};
  const float* hsrc = g_h1s + (size_t)s * BSZ * HSZ;

  for (int k0 = 0; k0 < HSZ; k0 += 64) {
    __syncthreads();
#pragma unroll
    for (int qq = 0; qq < 2; ++qq) {
      int idx = tid + qq * 256;
      int row = idx >> 4, kq = idx & 15;
      float4 v = *(const float4*)(hsrc + (size_t)(b0 + row) * HSZ + k0 + kq * 4);
      hs[row][kq * 4 + 0] = v.x; hs[row][kq * 4 + 1] = v.y;
      hs[row][kq * 4 + 2] = v.z; hs[row][kq * 4 + 3] = v.w;
      float4 w = *(const float4*)(Wout + (size_t)row * HSZ + k0 + kq * 4);
      wsT[kq * 4 + 0][row] = w.x; wsT[kq * 4 + 1][row] = w.y;
      wsT[kq * 4 + 2][row] = w.z; wsT[kq * 4 + 3][row] = w.w;
    }
    __syncthreads();
#pragma unroll 8
    for (int kk = 0; kk < 64; ++kk) {
      float hv = hs[bloc][kk];
      float4 w = *(const float4*)&wsT[kk][f0];
      acc[0] += hv * w.x; acc[1] += hv * w.y;
      acc[2] += hv * w.z; acc[3] += hv * w.w;
    }
  }
  float* op = out + (size_t)(b0 + bloc) * TOUT * FSZ + s * FSZ + f0;
  op[0] = acc[0] + bout[f0 + 0];
  op[1] = acc[1] + bout[f0 + 1];
  op[2] = acc[2] + bout[f0 + 2];
  op[3] = acc[3] + bout[f0 + 3];
}

// ---------------- host ----------------
template <typename T>
static T* sym_addr(const void* sym) {
  void* p = nullptr;
  cudaGetSymbolAddress(&p, sym);
  return (T*)p;
}

extern "C" void kernel_launch(void* const* d_in, const int* in_sizes, int n_in,
                              void* d_out, int out_size) {
  (void)in_sizes; (void)n_in; (void)out_size;
  const float* x     = (const float*)d_in[0];
  const float* eWih0 = (const float*)d_in[1];
  const float* eWhh0 = (const float*)d_in[2];
  const float* eb0   = (const float*)d_in[3];
  const float* eWih1 = (const float*)d_in[4];
  const float* eWhh1 = (const float*)d_in[5];
  const float* eb1   = (const float*)d_in[6];
  const float* dWih0 = (const float*)d_in[7];
  const float* dWhh0 = (const float*)d_in[8];
  const float* db0   = (const float*)d_in[9];
  const float* dWih1 = (const float*)d_in[10];
  const float* dWhh1 = (const float*)d_in[11];
  const float* db1   = (const float*)d_in[12];
  const float* dWout = (const float*)d_in[13];
  const float* dbout = (const float*)d_in[14];

  uint32_t* h0hi = sym_addr<uint32_t>(g_h0hi);
  uint32_t* h0lo = sym_addr<uint32_t>(g_h0lo);
  uint32_t* h1hi = sym_addr<uint32_t>(g_h1hi);
  uint32_t* h1lo = sym_addr<uint32_t>(g_h1lo);
  float* c0 = sym_addr<float>(g_c0);
  float* c1 = sym_addr<float>(g_c1);
  uint32_t* xhi = sym_addr<uint32_t>(g_xhi);
  uint32_t* xlo = sym_addr<uint32_t>(g_xlo);
  float* Wp = sym_addr<float>(g_Wp);
  float* bp = sym_addr<float>(g_bp);
  float* h1s = sym_addr<float>(g_h1s);

  uint32_t* eWih0h = sym_addr<uint32_t>(g_eWih0h); uint32_t* eWih0l = sym_addr<uint32_t>(g_eWih0l);
  uint32_t* eWhh0h = sym_addr<uint32_t>(g_eWhh0h); uint32_t* eWhh0l = sym_addr<uint32_t>(g_eWhh0l);
  uint32_t* eWih1h = sym_addr<uint32_t>(g_eWih1h); uint32_t* eWih1l = sym_addr<uint32_t>(g_eWih1l);
  uint32_t* eWhh1h = sym_addr<uint32_t>(g_eWhh1h); uint32_t* eWhh1l = sym_addr<uint32_t>(g_eWhh1l);
  uint32_t* dWih0h = sym_addr<uint32_t>(g_dWih0h); uint32_t* dWih0l = sym_addr<uint32_t>(g_dWih0l);
  uint32_t* dWhh0h = sym_addr<uint32_t>(g_dWhh0h); uint32_t* dWhh0l = sym_addr<uint32_t>(g_dWhh0l);
  uint32_t* dWih1h = sym_addr<uint32_t>(g_dWih1h); uint32_t* dWih1l = sym_addr<uint32_t>(g_dWih1l);
  uint32_t* dWhh1h = sym_addr<uint32_t>(g_dWhh1h); uint32_t* dWhh1l = sym_addr<uint32_t>(g_dWhh1l);
  uint32_t* Wph = sym_addr<uint32_t>(g_Wph);       uint32_t* Wpl = sym_addr<uint32_t>(g_Wpl);

  const int pW = BSZ * PH;          // packed words per h buffer
  const int pN = BSZ * HSZ;
  const int ldx = TIN * PX;
  dim3 grid(BSZ / 32, HSZ / 16);

  zero_init_kernel<<<(BSZ * HSZ) / 256, 256>>>();
  wp_kernel<<<4 * HSZ, 256>>>(dWih0, dWout);
  bp_kernel<<<(4 * HSZ) / 256, 256>>>(dWih0, db0, dbout);
  pack_x<<<(BSZ * TIN * PX) / 256, 256>>>(x);
  pack_w<<<(1024 * 16) / 256, 256>>>(eWih0, 32, eWih0h, eWih0l);
  pack_w<<<(1024 * 128) / 256, 256>>>(eWhh0, 256, eWhh0h, eWhh0l);
  pack_w<<<(1024 * 128) / 256, 256>>>(eWih1, 256, eWih1h, eWih1l);
  pack_w<<<(1024 * 128) / 256, 256>>>(eWhh1, 256, eWhh1h, eWhh1l);
  pack_w<<<(1024 * 16) / 256, 256>>>(dWih0, 32, dWih0h, dWih0l);
  pack_w<<<(1024 * 128) / 256, 256>>>(dWhh0, 256, dWhh0h, dWhh0l);
  pack_w<<<(1024 * 128) / 256, 256>>>(dWih1, 256, dWih1h, dWih1l);
  pack_w<<<(1024 * 128) / 256, 256>>>(dWhh1, 256, dWhh1h, dWhh1l);
  pack_w<<<(1024 * 128) / 256, 256>>>(Wp, 256, Wph, Wpl);

  int par = 0;
  // -------- encoder --------
  for (int t = 0; t < TIN; ++t) {
    lstm_step<<<grid, 256>>>(xhi + (size_t)t * PX, xlo + (size_t)t * PX,
                             ldx, PX, eWih0h, eWih0l,
                             h0hi + par * pW, h0lo + par * pW,
                             eWhh0h, eWhh0l, eb0, c0,
                             h0hi + (par ^ 1) * pW, h0lo + (par ^ 1) * pW,
                             nullptr);
    lstm_step<<<grid, 256>>>(h0hi + (par ^ 1) * pW, h0lo + (par ^ 1) * pW,
                             PH, PH, eWih1h, eWih1l,
                             h1hi + par * pW, h1lo + par * pW,
                             eWhh1h, eWhh1l, eb1, c1,
                             h1hi + (par ^ 1) * pW, h1lo + (par ^ 1) * pW,
                             nullptr);
    par ^= 1;
  }
  // -------- decoder --------
  for (int s = 0; s < TOUT; ++s) {
    if (s == 0) {
      lstm_step<<<grid, 256>>>(xhi + (size_t)(TIN - 1) * PX,
                               xlo + (size_t)(TIN - 1) * PX,
                               ldx, PX, dWih0h, dWih0l,
                               h0hi + par * pW, h0lo + par * pW,
                               dWhh0h, dWhh0l, db0, c0,
                               h0hi + (par ^ 1) * pW, h0lo + (par ^ 1) * pW,
                               nullptr);
    } else {
      // y-feedback folded: W' = dec_Wih0 @ dec_Wout, b' = dec_b0 + dec_Wih0 @ dec_bout
      lstm_step<<<grid, 256>>>(h1hi + par * pW, h1lo + par * pW,
                               PH, PH, Wph, Wpl,
                               h0hi + par * pW, h0lo + par * pW,
                               dWhh0h, dWhh0l, bp, c0,
                               h0hi + (par ^ 1) * pW, h0lo + (par ^ 1) * pW,
                               nullptr);
    }
    lstm_step<<<grid, 256>>>(h0hi + (par ^ 1) * pW, h0lo + (par ^ 1) * pW,
                             PH, PH, dWih1h, dWih1l,
                             h1hi + par * pW, h1lo + par * pW,
                             dWhh1h, dWhh1l, db1, c1,
                             h1hi + (par ^ 1) * pW, h1lo + (par ^ 1) * pW,
                             h1s + (size_t)s * pN);
    par ^= 1;
  }
  // -------- output projection --------
  out_proj<<<dim3(BSZ / 32, TOUT), 256>>>(dWout, dbout, (float*)d_out);
}